// round 12
// baseline (speedup 1.0000x reference)
#include <cuda_runtime.h>

// Depthwise separable 4x4 blur, filter [1,3,3,1] (x) [1,3,3,1] / 64.
// Input  (8, 256, 64, 512) fp32, W-pad circular(1), H-pad reflect(1).
// Output (8, 256, 63, 511) fp32.
//
// R12 = R11 (8-deep register prefetch ring, ldcs/stcs, 92.6us) with
// __launch_bounds__(128, 6): force <=~84 regs so a 6th CTA fits per SM.
// Ring-resident in-flight read bytes 160KB -> 192KB per SM (+20%); ptxas
// should rematerialize address math rather than spill the 64-reg ring.

#define W      512
#define H      64
#define OW     511
#define OH     63
#define DEPTH  8

__device__ __forceinline__ float4 f4_vblur(const float4& a, const float4& b,
                                           const float4& c, const float4& d)
{
    float4 r;
    r.x = ((a.x + d.x) + 3.0f * (b.x + c.x)) * (1.0f / 64.0f);
    r.y = ((a.y + d.y) + 3.0f * (b.y + c.y)) * (1.0f / 64.0f);
    r.z = ((a.z + d.z) + 3.0f * (b.z + c.z)) * (1.0f / 64.0f);
    r.w = ((a.w + d.w) + 3.0f * (b.w + c.w)) * (1.0f / 64.0f);
    return r;
}

__device__ __forceinline__ float4 f4_hblur(const float4& A, const float4& B)
{
    // outputs ox = 4t+1..4t+4 from src cols A=[4t..4t+3], B=[4t+4..4t+7]
    float4 r;
    r.x = (A.x + A.w) + 3.0f * (A.y + A.z);
    r.y = (A.y + B.x) + 3.0f * (A.z + A.w);
    r.z = (A.z + B.y) + 3.0f * (A.w + B.x);
    r.w = (A.w + B.z) + 3.0f * (B.x + B.y);
    return r;
}

__global__ __launch_bounds__(128, 6) void Blur_49976239456711_kernel(
    const float* __restrict__ in, float* __restrict__ out)
{
    const int t   = threadIdx.x;           // 0..127, owns src cols 4t..4t+3
    const int img = blockIdx.x;            // 0..2047

    const float* __restrict__ src = in  + (size_t)img * (H * W);
    float*       __restrict__ dst = out + (size_t)img * (OH * OW);

    const int cA = 4 * t;
    const int cB = (4 * t + 4) & (W - 1);  // wraps 512 -> 0 for t=127

    const int  ox0  = 4 * t + 1;
    const bool full = (t < 127);            // t=127 covers ox 509,510,(skip),0

    auto store4 = [&](int oy, const float4& v) {
        float* row = dst + oy * OW;
        __stcs(row + ox0,     v.x);
        __stcs(row + ox0 + 1, v.y);
        if (full) {
            __stcs(row + ox0 + 2, v.z);
            __stcs(row + ox0 + 3, v.w);
        } else {
            __stcs(row + 0, v.w);           // circular wrap: ox=0
        }
    };

    // ── 8-deep prefetch ring: slot s holds a src row, loaded 8 iters ahead ──
    float4 pa[DEPTH], pb[DEPTH];

    auto issue = [&](int y, int s) {
        pa[s] = __ldcs(reinterpret_cast<const float4*>(src + y * W + cA));
        pb[s] = __ldcs(reinterpret_cast<const float4*>(src + y * W + cB));
    };

    // Prologue: prefetch rows 2..9 into slots 0..7 (consumed at oy = 0..7).
    #pragma unroll
    for (int s = 0; s < DEPTH; ++s) issue(s + 2, s);

    // Initial vertical window (reflect: padded 0 -> src 1, padded 1 -> src 0,
    // padded 2 -> src 1). Direct loads for src rows 1 and 0.
    const float4 A1 = __ldcs(reinterpret_cast<const float4*>(src + 1 * W + cA));
    const float4 B1 = __ldcs(reinterpret_cast<const float4*>(src + 1 * W + cB));
    const float4 A0 = __ldcs(reinterpret_cast<const float4*>(src + 0 * W + cA));
    const float4 B0 = __ldcs(reinterpret_cast<const float4*>(src + 0 * W + cB));

    float4 hb0 = f4_hblur(A1, B1);   // HB[padded 0] = src row 1
    float4 hb1 = f4_hblur(A0, B0);   // HB[padded 1] = src row 0
    float4 hb2 = hb0;                // HB[padded 2] = src row 1
    float4 hb3;

    // Main loop: 56 trips, unroll 8 -> ring index oy&7 is static in every
    // unrolled body position. Output oy consumes src row oy+2 from slot
    // (oy&7), then refills that slot with src row oy+10 (rows 10..63).
    #pragma unroll 8
    for (int oy = 0; oy < 56; ++oy) {
        const int s = oy & (DEPTH - 1);
        hb3 = f4_hblur(pa[s], pb[s]);              // src row oy+2
        const int ny = oy + 10;
        if (ny < H) issue(ny, s);                  // oy <= 53
        store4(oy, f4_vblur(hb0, hb1, hb2, hb3));
        hb0 = hb1; hb1 = hb2; hb2 = hb3;
    }

    // Peeled tail oy = 56..61: fully unrolled, static slot indices, no refills.
    #pragma unroll
    for (int oy = 56; oy < 62; ++oy) {
        const int s = oy & (DEPTH - 1);
        hb3 = f4_hblur(pa[s], pb[s]);              // src row oy+2
        store4(oy, f4_vblur(hb0, hb1, hb2, hb3));
        hb0 = hb1; hb1 = hb2; hb2 = hb3;
    }

    // oy = 62: padded rows 62..65 -> src 61,62,63,62 -> window (hb0,hb1,hb2,hb1).
    {
        float4 o;
        o.x = ((hb0.x + hb1.x) + 3.0f * (hb1.x + hb2.x)) * (1.0f / 64.0f);
        o.y = ((hb0.y + hb1.y) + 3.0f * (hb1.y + hb2.y)) * (1.0f / 64.0f);
        o.z = ((hb0.z + hb1.z) + 3.0f * (hb1.z + hb2.z)) * (1.0f / 64.0f);
        o.w = ((hb0.w + hb1.w) + 3.0f * (hb1.w + hb2.w)) * (1.0f / 64.0f);
        store4(OH - 1, o);
    }
}

extern "C" void kernel_launch(void* const* d_in, const int* in_sizes, int n_in,
                              void* d_out, int out_size)
{
    const float* h = (const float*)d_in[0];
    float* out = (float*)d_out;

    const int n_img = 8 * 256;              // 2048 images of 64x512
    Blur_49976239456711_kernel<<<n_img, 128>>>(h, out);
}